// round 4
// baseline (speedup 1.0000x reference)
#include <cuda_runtime.h>
#include <math.h>

// CPABActivationDifferent: out[n][c] = cpab_transform(x[n][c]; theta[c])
// Elementwise map; argsort/unsort in the reference is value-identity.
//
// B_BASIS reproduction: numpy.linalg.svd -> dgesdd, M=17 < N=32, N >= MNTHR(31)
// => rows 17..31 of Vt are rows 17..31 of the full Q from the LQ factorization
// (dgelq2 unblocked + dorgl2), reimplemented in fp64.
//
// Main kernel works in q = 16*p coordinates (exact power-of-2 scaling => the
// closed-form iteration and all cell/stay decisions are bit-identical to the
// reference up to 1-ulp fma-vs-mul+add differences). Fully branchless step:
// both closed-form and 5 folded-FFMA Euler substeps are computed, selected at
// the end — removes BSSY/BSYNC divergence cost entirely.

#define NCELL 16
#define CH 256
#define LROWS 17
#define LCOLS 32
#define NNULL 15

__device__ float2 g_eg[NCELL * CH];   // (eta, 16*gamma)  closed-form, scaled
__device__ float2 g_eu[NCELL * CH];   // (1+ddt*a, 16*ddt*b)  folded Euler, scaled

__device__ __forceinline__ float decode_time(const void* tptr) {
    int iv = *(const int*)tptr;
    float fv = __int_as_float(iv);
    float af = fabsf(fv);
    if (af >= 1e-6f && af <= 1e6f) return fv;
    return (float)iv;
}

__device__ __forceinline__ double warp_sum(double v) {
    #pragma unroll
    for (int off = 16; off; off >>= 1)
        v += __shfl_xor_sync(0xffffffffu, v, off);
    return v;
}

// ---------------------------------------------------------------------------
// Precompute: LAPACK-faithful null basis + per-channel coefficient tables.
// ---------------------------------------------------------------------------
__global__ void cpab_precompute_kernel(const float* __restrict__ theta,
                                       const void* __restrict__ timep) {
    __shared__ double sM[LROWS][LCOLS];
    __shared__ double stau[LROWS];
    __shared__ double sQ[NNULL][LCOLS];

    const int tid  = threadIdx.x;
    const int lane = tid & 31;
    const int w    = tid >> 5;

    for (int i = tid; i < LROWS * LCOLS; i += blockDim.x)
        ((double*)sM)[i] = 0.0;
    __syncthreads();
    if (tid == 0) {
        for (int k = 1; k < NCELL; k++) {
            double xk = (double)k / (double)NCELL;
            sM[k - 1][2 * (k - 1)]     =  xk;
            sM[k - 1][2 * (k - 1) + 1] =  1.0;
            sM[k - 1][2 * k]           = -xk;
            sM[k - 1][2 * k + 1]       = -1.0;
        }
        sM[NCELL - 1][1] = 1.0;
        sM[NCELL][2 * NCELL - 2] = 1.0;
        sM[NCELL][2 * NCELL - 1] = 1.0;
    }
    __syncthreads();

    // dgelq2: unblocked Householder LQ (LAPACK sign conventions).
    for (int i = 0; i < LROWS; i++) {
        if (w == 0) {
            double aij = sM[i][lane];
            double sq  = (lane > i) ? aij * aij : 0.0;
            sq = warp_sum(sq);
            double alpha = __shfl_sync(0xffffffffu, aij, i);
            double xnorm = sqrt(sq);
            double tau = 0.0;
            if (xnorm != 0.0) {
                double aa = fabs(alpha);
                double wv = fmax(aa, xnorm), zv = fmin(aa, xnorm);
                double r  = (zv == 0.0) ? wv : wv * sqrt(1.0 + (zv / wv) * (zv / wv));
                double beta = (alpha >= 0.0) ? -r : r;
                tau = (beta - alpha) / beta;
                double inv = 1.0 / (alpha - beta);
                if (lane > i)  sM[i][lane] = aij * inv;
                if (lane == i) sM[i][i] = beta;
            }
            if (lane == 0) stau[i] = tau;
        }
        __syncthreads();
        int r = i + 1 + w;
        if (r < LROWS) {
            double tau = stau[i];
            if (tau != 0.0) {
                double v   = (lane == i) ? 1.0 : ((lane > i) ? sM[i][lane] : 0.0);
                double arj = (lane >= i) ? sM[r][lane] : 0.0;
                double dot = warp_sum(arj * v);
                if (lane >= i) sM[r][lane] = arj - tau * dot * v;
            }
        }
        __syncthreads();
    }

    // dorgl2: rows 17..31 of Q.
    if (w < NNULL) {
        int r = LROWS + w;
        double q = (lane == r) ? 1.0 : 0.0;
        for (int i = LROWS - 1; i >= 0; i--) {
            double tau = stau[i];
            double v = (lane == i) ? 1.0 : ((lane > i) ? sM[i][lane] : 0.0);
            double dot = warp_sum(q * v);
            q -= tau * dot * v;
        }
        sQ[w][lane] = q;
    }
    __syncthreads();

    // Per-channel coefficient tables (scaled by 16 for q-coordinates).
    if (tid < CH) {
        const int c = tid;
        float tf  = decode_time(timep);
        float dt  = tf / 10.0f;
        float ddt = dt / 5.0f;
        float A[LCOLS];
        #pragma unroll
        for (int j = 0; j < LCOLS; j++) {
            float s = 0.0f;
            #pragma unroll
            for (int cc = 0; cc < NNULL; cc++)
                s += theta[c * NNULL + cc] * (float)sQ[cc][j];
            A[j] = s;
        }
        #pragma unroll
        for (int k = 0; k < NCELL; k++) {
            float a = A[2 * k], b = A[2 * k + 1];
            float eta, gam;
            if (fabsf(a) > 1e-7f) {
                eta = expf(dt * a);
                gam = __fmul_rn(__fdiv_rn(b, a), __fsub_rn(eta, 1.0f));
            } else {
                eta = 1.0f;
                gam = __fmul_rn(b, dt);
            }
            g_eg[k * CH + c] = make_float2(eta, __fmul_rn(gam, 16.0f));
            float eb = __fmul_rn(ddt, b);
            g_eu[k * CH + c] = make_float2(__fadd_rn(1.0f, __fmul_rn(ddt, a)),
                                           __fmul_rn(eb, 16.0f));
        }
    }
}

// ---------------------------------------------------------------------------
// Main elementwise transform (branchless, q = 16*p coordinates).
// ---------------------------------------------------------------------------
__device__ __forceinline__ float cpab_one(float xv,
                                          const float2* __restrict__ egc,
                                          const float2* __restrict__ euc) {
    float s = __fmaf_rn(xv, 1.0f / 6.0f, 0.5f);       // (x+3)/6
    bool ood = (s >= 1.0f) || (s <= 0.0f);
    float q = ood ? 8.0f : __fmul_rn(s, 16.0f);        // exact 16*s; dummy if ood
    #pragma unroll 1
    for (int st = 0; st < 10; ++st) {
        q = fmaxf(q, 0.0f);                            // robustness (1 instr)
        int c0 = min((int)q, 15);                      // trunc ok: q > -1
        float2 g = egc[c0 << 8];
        float qc = __fmaf_rn(g.x, q, g.y);             // closed-form step
        int c1 = min((int)qc, 15);                     // only used for compare
        float qe = q;
        #pragma unroll
        for (int ss = 0; ss < 5; ++ss) {               // folded Euler substeps
            int cc = min((int)qe, 15);
            float2 u = euc[cc << 8];
            qe = __fmaf_rn(u.x, qe, u.y);
        }
        q = (c1 == c0) ? qc : qe;                      // branchless select
    }
    return ood ? xv : __fmaf_rn(q, 0.375f, -3.0f);     // q*(6/16) - 3
}

__global__ void __launch_bounds__(1024, 2)
cpab_main_kernel(const float4* __restrict__ x4,
                 const float* __restrict__ x,
                 const float* __restrict__ theta,
                 float4* __restrict__ out4,
                 float* __restrict__ out,
                 int n4, long long n, int ntheta) {
    extern __shared__ float2 sh[];
    float2* s_eg = sh;
    float2* s_eu = sh + NCELL * CH;
    for (int i = threadIdx.x; i < NCELL * CH; i += blockDim.x) {
        s_eg[i] = g_eg[i];
        s_eu[i] = g_eu[i];
    }
    __syncthreads();

    const int tid    = blockIdx.x * blockDim.x + threadIdx.x;
    const int stride = gridDim.x * blockDim.x;

    // theta passthrough tail of the output
    for (int t = tid; t < ntheta; t += stride)
        out[n + t] = theta[t];

    // scalar tail (n not divisible by 4) — block 0 only
    const int rem = (int)(n - (long long)n4 * 4);
    if (blockIdx.x == 0) {
        for (int t = threadIdx.x; t < rem; t += blockDim.x) {
            long long i = (long long)n4 * 4 + t;
            int c = (int)(i & (CH - 1));
            out[i] = cpab_one(x[i], s_eg + c, s_eu + c);
        }
    }

    // vectorized main loop: 4 consecutive channels per float4 (CH % 4 == 0)
    for (int i = tid; i < n4; i += stride) {
        float4 v = __ldg(x4 + i);
        int cb = (i << 2) & (CH - 1);
        float4 r;
        r.x = cpab_one(v.x, s_eg + cb + 0, s_eu + cb + 0);
        r.y = cpab_one(v.y, s_eg + cb + 1, s_eu + cb + 1);
        r.z = cpab_one(v.z, s_eg + cb + 2, s_eu + cb + 2);
        r.w = cpab_one(v.w, s_eg + cb + 3, s_eu + cb + 3);
        out4[i] = r;
    }
}

extern "C" void kernel_launch(void* const* d_in, const int* in_sizes, int n_in,
                              void* d_out, int out_size) {
    const float* x     = (const float*)d_in[0];
    const void*  timep = d_in[4];
    const float* theta = (const float*)d_in[5];
    float* out = (float*)d_out;

    const long long n = (long long)in_sizes[0];
    const int ntheta = out_size - (int)n;
    const int n4 = (int)(n >> 2);

    cpab_precompute_kernel<<<1, 512>>>(theta, timep);

    // Immediate (non-stream) API; idempotent, safe under graph capture.
    cudaFuncSetAttribute(cpab_main_kernel,
                         cudaFuncAttributeMaxDynamicSharedMemorySize,
                         (int)(2 * NCELL * CH * sizeof(float2)));

    const int threads = 1024;
    const int blocks  = 304;   // 152 SMs * 2 CTAs (64KB smem each)
    const size_t smem = 2 * NCELL * CH * sizeof(float2);
    cpab_main_kernel<<<blocks, threads, smem>>>(
        (const float4*)x, x, theta, (float4*)out, out, n4, n, ntheta);
}

// round 5
// speedup vs baseline: 2.3346x; 2.3346x over previous
#include <cuda_runtime.h>
#include <math.h>

// CPABActivationDifferent: out[n][c] = cpab_transform(x[n][c]; theta[c]).
// Elementwise map; the reference's argsort/unsort is value-identity.
//
// B_BASIS: numpy.linalg.svd -> dgesdd, M=17 < N=32 >= MNTHR(31) => rows 17..31
// of Vt are rows 17..31 of the full Q of the LQ factorization (dgelq2+dorgl2),
// reimplemented faithfully in fp64. Each block recomputes it (cheap, parallel)
// so the whole problem is ONE kernel launch.
//
// Main loop works in q = 16*p coordinates (exact *16 scaling) with trunc-based
// cell lookup; Euler fallback folded to one FFMA per substep and executed only
// when some lane in the warp crosses a cell (warp-uniform branch, no BSSY).

#define NCELL 16
#define CH 256
#define LROWS 17
#define LCOLS 32
#define NNULL 15

__device__ __forceinline__ float decode_time(const void* tptr) {
    int iv = *(const int*)tptr;
    float fv = __int_as_float(iv);
    float af = fabsf(fv);
    if (af >= 1e-6f && af <= 1e6f) return fv;
    return (float)iv;
}

__device__ __forceinline__ double warp_sum(double v) {
    #pragma unroll
    for (int off = 16; off; off >>= 1)
        v += __shfl_xor_sync(0xffffffffu, v, off);
    return v;
}

// Dynamic smem layout
struct SmemLayout {
    float2 eg[NCELL * CH];      // (eta, 16*gamma)       closed-form, scaled
    float2 eu[NCELL * CH];      // (1+ddt*a, 16*ddt*b)   folded Euler, scaled
    double M[LROWS][LCOLS];
    double tau[LROWS];
    double Q[NNULL][LCOLS];
};

__global__ void __launch_bounds__(512, 3)
cpab_kernel(const float* __restrict__ x,
            const float* __restrict__ theta,
            const void*  __restrict__ timep,
            float* __restrict__ out,
            long long n, int ntheta) {
    extern __shared__ char smem_raw[];
    SmemLayout* S = (SmemLayout*)smem_raw;

    const int tid  = threadIdx.x;
    const int lane = tid & 31;
    const int w    = tid >> 5;

    // ---- per-block precompute: LAPACK-faithful null basis (fp64) ----
    for (int i = tid; i < LROWS * LCOLS; i += blockDim.x)
        ((double*)S->M)[i] = 0.0;
    __syncthreads();
    if (tid == 0) {
        for (int k = 1; k < NCELL; k++) {
            double xk = (double)k / (double)NCELL;
            S->M[k - 1][2 * (k - 1)]     =  xk;
            S->M[k - 1][2 * (k - 1) + 1] =  1.0;
            S->M[k - 1][2 * k]           = -xk;
            S->M[k - 1][2 * k + 1]       = -1.0;
        }
        S->M[NCELL - 1][1] = 1.0;
        S->M[NCELL][2 * NCELL - 2] = 1.0;
        S->M[NCELL][2 * NCELL - 1] = 1.0;
    }
    __syncthreads();

    // dgelq2 (unblocked Householder LQ, LAPACK sign conventions)
    for (int i = 0; i < LROWS; i++) {
        if (w == 0) {
            double aij = S->M[i][lane];
            double sq  = (lane > i) ? aij * aij : 0.0;
            sq = warp_sum(sq);
            double alpha = __shfl_sync(0xffffffffu, aij, i);
            double xnorm = sqrt(sq);
            double tau = 0.0;
            if (xnorm != 0.0) {
                double aa = fabs(alpha);
                double wv = fmax(aa, xnorm), zv = fmin(aa, xnorm);
                double r  = (zv == 0.0) ? wv
                            : wv * sqrt(1.0 + (zv / wv) * (zv / wv));
                double beta = (alpha >= 0.0) ? -r : r;
                tau = (beta - alpha) / beta;
                double inv = 1.0 / (alpha - beta);
                if (lane > i)  S->M[i][lane] = aij * inv;
                if (lane == i) S->M[i][i] = beta;
            }
            if (lane == 0) S->tau[i] = tau;
        }
        __syncthreads();
        int r = i + 1 + w;
        if (r < LROWS) {
            double tau = S->tau[i];
            if (tau != 0.0) {
                double v   = (lane == i) ? 1.0
                             : ((lane > i) ? S->M[i][lane] : 0.0);
                double arj = (lane >= i) ? S->M[r][lane] : 0.0;
                double dot = warp_sum(arj * v);
                if (lane >= i) S->M[r][lane] = arj - tau * dot * v;
            }
        }
        __syncthreads();
    }

    // dorgl2: rows 17..31 of Q
    if (w < NNULL) {
        int r = LROWS + w;
        double q = (lane == r) ? 1.0 : 0.0;
        for (int i = LROWS - 1; i >= 0; i--) {
            double tau = S->tau[i];
            double v = (lane == i) ? 1.0 : ((lane > i) ? S->M[i][lane] : 0.0);
            double dot = warp_sum(q * v);
            q -= tau * dot * v;
        }
        S->Q[w][lane] = q;
    }
    __syncthreads();

    // Per-channel coefficient tables (scaled for q = 16*p coordinates)
    if (tid < CH) {
        const int c = tid;
        float tf  = decode_time(timep);
        float dt  = tf / 10.0f;
        float ddt = dt / 5.0f;
        float A[LCOLS];
        #pragma unroll
        for (int j = 0; j < LCOLS; j++) {
            float s = 0.0f;
            #pragma unroll
            for (int cc = 0; cc < NNULL; cc++)
                s += theta[c * NNULL + cc] * (float)S->Q[cc][j];
            A[j] = s;
        }
        #pragma unroll
        for (int k = 0; k < NCELL; k++) {
            float a = A[2 * k], b = A[2 * k + 1];
            float eta, gam;
            if (fabsf(a) > 1e-7f) {
                eta = expf(dt * a);
                gam = __fmul_rn(__fdiv_rn(b, a), __fsub_rn(eta, 1.0f));
            } else {
                eta = 1.0f;
                gam = __fmul_rn(b, dt);
            }
            S->eg[k * CH + c] = make_float2(eta, __fmul_rn(gam, 16.0f));
            S->eu[k * CH + c] = make_float2(__fadd_rn(1.0f, __fmul_rn(ddt, a)),
                                            __fmul_rn(__fmul_rn(ddt, b), 16.0f));
        }
    }
    __syncthreads();

    // ---- main elementwise loop ----
    const long long stride = (long long)gridDim.x * blockDim.x;
    const long long i0 = (long long)blockIdx.x * blockDim.x + tid;

    for (long long t = i0; t < ntheta; t += stride)
        out[n + t] = theta[t];

    const float2* __restrict__ s_eg = S->eg;
    const float2* __restrict__ s_eu = S->eu;

    // index-clamped grid-stride: every lane of every warp stays active, so
    // __any_sync(0xffffffff, ...) below is always valid.
    for (long long i = i0; i < n; i += stride) {
        long long ic = i < n ? i : n - 1;      // i < n by loop cond; keep safe
        float xv = __ldg(x + ic);
        const int c = (int)(ic & (CH - 1));

        float s = __fmaf_rn(xv, 1.0f / 6.0f, 0.5f);  // (x+3)/6
        bool ood = (s >= 1.0f) || (s <= 0.0f);
        float q = ood ? 8.0f : __fmul_rn(s, 16.0f);  // exact 16*s

        #pragma unroll 1
        for (int st = 0; st < 10; ++st) {
            int c0 = min((int)q, 15);                 // trunc==floor+clip (q>-1)
            float2 g = s_eg[(c0 << 8) + c];
            float qc = __fmaf_rn(g.x, q, g.y);        // closed-form step
            int c1 = min((int)qc, 15);
            bool cross = (c1 != c0);
            if (__any_sync(0xffffffffu, cross)) {     // warp-uniform branch
                float qe = q;
                #pragma unroll
                for (int ss = 0; ss < 5; ++ss) {      // folded Euler substeps
                    int cc = min((int)qe, 15);
                    float2 u = s_eu[(cc << 8) + c];
                    qe = __fmaf_rn(u.x, qe, u.y);
                }
                q = cross ? qe : qc;
            } else {
                q = qc;
            }
        }
        float res = ood ? xv : __fmaf_rn(q, 0.375f, -3.0f);  // q*6/16 - 3
        out[i] = res;
    }
}

extern "C" void kernel_launch(void* const* d_in, const int* in_sizes, int n_in,
                              void* d_out, int out_size) {
    const float* x     = (const float*)d_in[0];
    const void*  timep = d_in[4];
    const float* theta = (const float*)d_in[5];
    float* out = (float*)d_out;

    const long long n = (long long)in_sizes[0];
    const int ntheta = out_size - (int)n;

    const size_t smem = sizeof(SmemLayout);
    // Immediate (non-stream) API; idempotent, safe under graph capture.
    cudaFuncSetAttribute(cpab_kernel,
                         cudaFuncAttributeMaxDynamicSharedMemorySize,
                         (int)smem);

    const int threads = 512;
    const int blocks  = 456;   // 152 SMs * 3 CTAs (~73KB smem each)
    cpab_kernel<<<blocks, threads, smem>>>(x, theta, timep, out, n, ntheta);
}

// round 6
// speedup vs baseline: 2.8885x; 1.2373x over previous
#include <cuda_runtime.h>
#include <math.h>

// CPABActivationDifferent: out[n][c] = cpab_transform(x[n][c]; theta[c]).
// Elementwise map; the reference's argsort/unsort is value-identity.
//
// B_BASIS: numpy.linalg.svd -> dgesdd, M=17 < N=32 >= MNTHR(31) => rows 17..31
// of Vt are rows 17..31 of the full Q of the LQ factorization (dgelq2+dorgl2),
// reimplemented faithfully in fp64. Each block recomputes it (cheap, parallel)
// so the whole problem is ONE kernel launch.
//
// Main loop: q = 16*p coordinates (exact *16 scaling), trunc-based cell
// lookup, folded 1-FFMA Euler substeps. Per-lane crossing probability is high
// => Euler is computed unconditionally and selected per lane (no vote, no
// branch). TWO independent chains per thread (elements i and i+TT, same
// channel since TT % 256 == 0) give the ILP needed to cover the
// F2I->LDS->FFMA latency chain that bound round 5 at issue=51%.

#define NCELL 16
#define CH 256
#define LROWS 17
#define LCOLS 32
#define NNULL 15

__device__ __forceinline__ float decode_time(const void* tptr) {
    int iv = *(const int*)tptr;
    float fv = __int_as_float(iv);
    float af = fabsf(fv);
    if (af >= 1e-6f && af <= 1e6f) return fv;
    return (float)iv;
}

__device__ __forceinline__ double warp_sum(double v) {
    #pragma unroll
    for (int off = 16; off; off >>= 1)
        v += __shfl_xor_sync(0xffffffffu, v, off);
    return v;
}

struct SmemLayout {
    float2 eg[NCELL * CH];      // (eta, 16*gamma)       closed-form, scaled
    float2 eu[NCELL * CH];      // (1+ddt*a, 16*ddt*b)   folded Euler, scaled
    double M[LROWS][LCOLS];
    double tau[LROWS];
    double Q[NNULL][LCOLS];
};

__global__ void __launch_bounds__(512, 2)
cpab_kernel(const float* __restrict__ x,
            const float* __restrict__ theta,
            const void*  __restrict__ timep,
            float* __restrict__ out,
            long long n, int ntheta) {
    extern __shared__ char smem_raw[];
    SmemLayout* S = (SmemLayout*)smem_raw;

    const int tid  = threadIdx.x;
    const int lane = tid & 31;
    const int w    = tid >> 5;

    // ---- per-block precompute: LAPACK-faithful null basis (fp64) ----
    for (int i = tid; i < LROWS * LCOLS; i += blockDim.x)
        ((double*)S->M)[i] = 0.0;
    __syncthreads();
    if (tid == 0) {
        for (int k = 1; k < NCELL; k++) {
            double xk = (double)k / (double)NCELL;
            S->M[k - 1][2 * (k - 1)]     =  xk;
            S->M[k - 1][2 * (k - 1) + 1] =  1.0;
            S->M[k - 1][2 * k]           = -xk;
            S->M[k - 1][2 * k + 1]       = -1.0;
        }
        S->M[NCELL - 1][1] = 1.0;
        S->M[NCELL][2 * NCELL - 2] = 1.0;
        S->M[NCELL][2 * NCELL - 1] = 1.0;
    }
    __syncthreads();

    // dgelq2 (unblocked Householder LQ, LAPACK sign conventions)
    for (int i = 0; i < LROWS; i++) {
        if (w == 0) {
            double aij = S->M[i][lane];
            double sq  = (lane > i) ? aij * aij : 0.0;
            sq = warp_sum(sq);
            double alpha = __shfl_sync(0xffffffffu, aij, i);
            double xnorm = sqrt(sq);
            double tau = 0.0;
            if (xnorm != 0.0) {
                double aa = fabs(alpha);
                double wv = fmax(aa, xnorm), zv = fmin(aa, xnorm);
                double r  = (zv == 0.0) ? wv
                            : wv * sqrt(1.0 + (zv / wv) * (zv / wv));
                double beta = (alpha >= 0.0) ? -r : r;
                tau = (beta - alpha) / beta;
                double inv = 1.0 / (alpha - beta);
                if (lane > i)  S->M[i][lane] = aij * inv;
                if (lane == i) S->M[i][i] = beta;
            }
            if (lane == 0) S->tau[i] = tau;
        }
        __syncthreads();
        int r = i + 1 + w;
        if (r < LROWS) {
            double tau = S->tau[i];
            if (tau != 0.0) {
                double v   = (lane == i) ? 1.0
                             : ((lane > i) ? S->M[i][lane] : 0.0);
                double arj = (lane >= i) ? S->M[r][lane] : 0.0;
                double dot = warp_sum(arj * v);
                if (lane >= i) S->M[r][lane] = arj - tau * dot * v;
            }
        }
        __syncthreads();
    }

    // dorgl2: rows 17..31 of Q
    if (w < NNULL) {
        int r = LROWS + w;
        double q = (lane == r) ? 1.0 : 0.0;
        for (int i = LROWS - 1; i >= 0; i--) {
            double tau = S->tau[i];
            double v = (lane == i) ? 1.0 : ((lane > i) ? S->M[i][lane] : 0.0);
            double dot = warp_sum(q * v);
            q -= tau * dot * v;
        }
        S->Q[w][lane] = q;
    }
    __syncthreads();

    // Per-channel coefficient tables (scaled for q = 16*p coordinates)
    if (tid < CH) {
        const int c = tid;
        float tf  = decode_time(timep);
        float dt  = tf / 10.0f;
        float ddt = dt / 5.0f;
        float A[LCOLS];
        #pragma unroll
        for (int j = 0; j < LCOLS; j++) {
            float s = 0.0f;
            #pragma unroll
            for (int cc = 0; cc < NNULL; cc++)
                s += theta[c * NNULL + cc] * (float)S->Q[cc][j];
            A[j] = s;
        }
        #pragma unroll
        for (int k = 0; k < NCELL; k++) {
            float a = A[2 * k], b = A[2 * k + 1];
            float eta, gam;
            if (fabsf(a) > 1e-7f) {
                eta = expf(dt * a);
                gam = __fmul_rn(__fdiv_rn(b, a), __fsub_rn(eta, 1.0f));
            } else {
                eta = 1.0f;
                gam = __fmul_rn(b, dt);
            }
            S->eg[k * CH + c] = make_float2(eta, __fmul_rn(gam, 16.0f));
            S->eu[k * CH + c] = make_float2(__fadd_rn(1.0f, __fmul_rn(ddt, a)),
                                            __fmul_rn(__fmul_rn(ddt, b), 16.0f));
        }
    }
    __syncthreads();

    // ---- main elementwise loop: 2 independent chains per thread ----
    const long long TT = (long long)gridDim.x * blockDim.x;  // % 256 == 0
    const long long i0 = (long long)blockIdx.x * blockDim.x + tid;

    for (long long t = i0; t < ntheta; t += TT)
        out[n + t] = theta[t];

    const float2* __restrict__ s_eg = S->eg;
    const float2* __restrict__ s_eu = S->eu;

    for (long long i = i0; i < n; i += 2 * TT) {
        const long long iB = i + TT;
        const bool vB = iB < n;
        const float xA = __ldg(x + i);
        const float xB = vB ? __ldg(x + iB) : 0.0f;

        // TT % 256 == 0 => both chains share one channel (and table pointers)
        const int c = (int)(i & (CH - 1));
        const float2* __restrict__ egp = s_eg + c;
        const float2* __restrict__ eup = s_eu + c;

        float sA = __fmaf_rn(xA, 1.0f / 6.0f, 0.5f);
        float sB = __fmaf_rn(xB, 1.0f / 6.0f, 0.5f);
        const bool oodA = (sA >= 1.0f) || (sA <= 0.0f);
        const bool oodB = (sB >= 1.0f) || (sB <= 0.0f);
        float qA = oodA ? 8.0f : __fmul_rn(sA, 16.0f);
        float qB = oodB ? 8.0f : __fmul_rn(sB, 16.0f);

        #pragma unroll 1
        for (int st = 0; st < 10; ++st) {
            // chain A: cell, closed-form, Euler substep 1 (same cell)
            const int a0 = min((int)qA, 15);
            const int aoff = a0 << 8;
            const float2 ga = egp[aoff];
            const float2 ua = eup[aoff];
            float qcA = __fmaf_rn(ga.x, qA, ga.y);
            float qeA = __fmaf_rn(ua.x, qA, ua.y);
            // chain B
            const int b0 = min((int)qB, 15);
            const int boff = b0 << 8;
            const float2 gb = egp[boff];
            const float2 ub = eup[boff];
            float qcB = __fmaf_rn(gb.x, qB, gb.y);
            float qeB = __fmaf_rn(ub.x, qB, ub.y);
            // Euler substeps 2..5, interleaved across chains
            #pragma unroll
            for (int ss = 1; ss < 5; ++ss) {
                const int ca = min((int)qeA, 15);
                const int cb = min((int)qeB, 15);
                const float2 va = eup[ca << 8];
                const float2 vb = eup[cb << 8];
                qeA = __fmaf_rn(va.x, qeA, va.y);
                qeB = __fmaf_rn(vb.x, qeB, vb.y);
            }
            // per-lane select: stay -> closed form, cross -> Euler
            const int a1 = min((int)qcA, 15);
            const int b1 = min((int)qcB, 15);
            qA = (a1 == a0) ? qcA : qeA;
            qB = (b1 == b0) ? qcB : qeB;
        }

        out[i] = oodA ? xA : __fmaf_rn(qA, 0.375f, -3.0f);
        if (vB)
            out[iB] = oodB ? xB : __fmaf_rn(qB, 0.375f, -3.0f);
    }
}

extern "C" void kernel_launch(void* const* d_in, const int* in_sizes, int n_in,
                              void* d_out, int out_size) {
    const float* x     = (const float*)d_in[0];
    const void*  timep = d_in[4];
    const float* theta = (const float*)d_in[5];
    float* out = (float*)d_out;

    const long long n = (long long)in_sizes[0];
    const int ntheta = out_size - (int)n;

    const size_t smem = sizeof(SmemLayout);
    // Immediate (non-stream) API; idempotent, safe under graph capture.
    cudaFuncSetAttribute(cpab_kernel,
                         cudaFuncAttributeMaxDynamicSharedMemorySize,
                         (int)smem);

    const int threads = 512;
    const int blocks  = 304;   // 152 SMs * 2 CTAs; TT = 155648 ≡ 0 (mod 256)
    cpab_kernel<<<blocks, threads, smem>>>(x, theta, timep, out, n, ntheta);
}

// round 7
// speedup vs baseline: 3.1727x; 1.0984x over previous
#include <cuda_runtime.h>
#include <math.h>

// CPABActivationDifferent: out[n][c] = cpab_transform(x[n][c]; theta[c]).
// Elementwise; the reference's argsort/unsort is value-identity.
//
// R6 finding: the iterative engine is smem-crossbar-bound (60 LDS.64/elem,
// 74% of cycles). This round replaces it for ~90% of elements with a
// precomputed piecewise-affine table: every branch of the CPAB iteration is
// affine in q, so for a fixed decision path the 10-step map is one affine
// q -> m*q + t. We tabulate (m,t) on 4096 bins/channel, validated by bitwise
// agreement of decision-path hash and composed (m,t) at both bin endpoints
// (monotonicity of the map brackets interior paths by endpoint paths).
// Elements in invalid (breakpoint) bins are compacted to a queue and solved
// with the full iterative engine in a second pass.
//
// B_BASIS: numpy.linalg.svd -> dgesdd, M=17 < N=32 >= MNTHR(31) => rows 17..31
// of Vt are rows 17..31 of the full Q of the LQ factorization (dgelq2+dorgl2),
// reimplemented faithfully in fp64.

#define NCELL 16
#define CH 256
#define LROWS 17
#define LCOLS 32
#define NNULL 15
#define KB 4096                 // bins per channel
#define QUEUE_CAP (1 << 26)
#define BUFCAP 16384            // per-block smem staging (64 KB)

__device__ float2 g_eg[NCELL * CH];   // (eta, 16*gamma)       closed-form
__device__ float2 g_eu[NCELL * CH];   // (1+ddt*a, 16*ddt*b)   folded Euler
__device__ int    g_flag;             // 1 if all Euler slopes > 0 (monotone)
__device__ int    g_qcount;
struct EndPt { float m, t; unsigned long long h; };
__device__ EndPt  g_ep[CH * (KB + 1)];   // ~16.8 MB
__device__ float2 g_bins[CH * KB];       // 8 MB (L2-resident)
__device__ int    g_queue[QUEUE_CAP];

__device__ __forceinline__ float decode_time(const void* tptr) {
    int iv = *(const int*)tptr;
    float fv = __int_as_float(iv);
    float af = fabsf(fv);
    if (af >= 1e-6f && af <= 1e6f) return fv;
    return (float)iv;
}

__device__ __forceinline__ double warp_sum(double v) {
    #pragma unroll
    for (int off = 16; off; off >>= 1)
        v += __shfl_xor_sync(0xffffffffu, v, off);
    return v;
}

__device__ __forceinline__ int cell16(float q) { return min((int)q, 15); }

// Full iterative engine (identical arithmetic to the passing R6 kernel).
__device__ __forceinline__ float cpab_iter(float q, int c,
                                           const float2* eg, const float2* eu) {
    #pragma unroll 1
    for (int st = 0; st < 10; ++st) {
        int c0 = cell16(q);
        float2 g = eg[(c0 << 8) + c];
        float2 u = eu[(c0 << 8) + c];
        float qc = __fmaf_rn(g.x, q, g.y);
        float qe = __fmaf_rn(u.x, q, u.y);
        #pragma unroll
        for (int ss = 1; ss < 5; ++ss) {
            int cc = cell16(qe);
            float2 v = eu[(cc << 8) + c];
            qe = __fmaf_rn(v.x, qe, v.y);
        }
        int c1 = cell16(qc);
        q = (c1 == c0) ? qc : qe;
    }
    return q;
}

// ---------------------------------------------------------------------------
// K1a: fp64 LQ null basis -> per-channel tables (global); reset counters.
// ---------------------------------------------------------------------------
__global__ void cpab_setup(const float* __restrict__ theta,
                           const void*  __restrict__ timep) {
    __shared__ double sM[LROWS][LCOLS];
    __shared__ double stau[LROWS];
    __shared__ double sQ[NNULL][LCOLS];

    const int tid  = threadIdx.x;
    const int lane = tid & 31;
    const int w    = tid >> 5;

    if (tid == 0) { g_qcount = 0; g_flag = 1; }

    for (int i = tid; i < LROWS * LCOLS; i += blockDim.x)
        ((double*)sM)[i] = 0.0;
    __syncthreads();
    if (tid == 0) {
        for (int k = 1; k < NCELL; k++) {
            double xk = (double)k / (double)NCELL;
            sM[k - 1][2 * (k - 1)]     =  xk;
            sM[k - 1][2 * (k - 1) + 1] =  1.0;
            sM[k - 1][2 * k]           = -xk;
            sM[k - 1][2 * k + 1]       = -1.0;
        }
        sM[NCELL - 1][1] = 1.0;
        sM[NCELL][2 * NCELL - 2] = 1.0;
        sM[NCELL][2 * NCELL - 1] = 1.0;
    }
    __syncthreads();

    for (int i = 0; i < LROWS; i++) {
        if (w == 0) {
            double aij = sM[i][lane];
            double sq  = (lane > i) ? aij * aij : 0.0;
            sq = warp_sum(sq);
            double alpha = __shfl_sync(0xffffffffu, aij, i);
            double xnorm = sqrt(sq);
            double tau = 0.0;
            if (xnorm != 0.0) {
                double aa = fabs(alpha);
                double wv = fmax(aa, xnorm), zv = fmin(aa, xnorm);
                double r  = (zv == 0.0) ? wv
                            : wv * sqrt(1.0 + (zv / wv) * (zv / wv));
                double beta = (alpha >= 0.0) ? -r : r;
                tau = (beta - alpha) / beta;
                double inv = 1.0 / (alpha - beta);
                if (lane > i)  sM[i][lane] = aij * inv;
                if (lane == i) sM[i][i] = beta;
            }
            if (lane == 0) stau[i] = tau;
        }
        __syncthreads();
        int r = i + 1 + w;
        if (r < LROWS) {
            double tau = stau[i];
            if (tau != 0.0) {
                double v   = (lane == i) ? 1.0
                             : ((lane > i) ? sM[i][lane] : 0.0);
                double arj = (lane >= i) ? sM[r][lane] : 0.0;
                double dot = warp_sum(arj * v);
                if (lane >= i) sM[r][lane] = arj - tau * dot * v;
            }
        }
        __syncthreads();
    }

    if (w < NNULL) {
        int r = LROWS + w;
        double q = (lane == r) ? 1.0 : 0.0;
        for (int i = LROWS - 1; i >= 0; i--) {
            double tau = stau[i];
            double v = (lane == i) ? 1.0 : ((lane > i) ? sM[i][lane] : 0.0);
            double dot = warp_sum(q * v);
            q -= tau * dot * v;
        }
        sQ[w][lane] = q;
    }
    __syncthreads();

    if (tid < CH) {
        const int c = tid;
        float tf  = decode_time(timep);
        float dt  = tf / 10.0f;
        float ddt = dt / 5.0f;
        float A[LCOLS];
        #pragma unroll
        for (int j = 0; j < LCOLS; j++) {
            float s = 0.0f;
            #pragma unroll
            for (int cc = 0; cc < NNULL; cc++)
                s += theta[c * NNULL + cc] * (float)sQ[cc][j];
            A[j] = s;
        }
        bool ok = true;
        #pragma unroll
        for (int k = 0; k < NCELL; k++) {
            float a = A[2 * k], b = A[2 * k + 1];
            float eta, gam;
            if (fabsf(a) > 1e-7f) {
                eta = expf(dt * a);
                gam = __fmul_rn(__fdiv_rn(b, a), __fsub_rn(eta, 1.0f));
            } else {
                eta = 1.0f;
                gam = __fmul_rn(b, dt);
            }
            float ex = __fadd_rn(1.0f, __fmul_rn(ddt, a));
            if (!(ex > 0.0f) || !(eta > 0.0f)) ok = false;
            g_eg[k * CH + c] = make_float2(eta, __fmul_rn(gam, 16.0f));
            g_eu[k * CH + c] = make_float2(ex,
                                           __fmul_rn(__fmul_rn(ddt, b), 16.0f));
        }
        if (!ok) g_flag = 0;   // race-free enough: only ever writes 0
    }
}

// ---------------------------------------------------------------------------
// K1b: evaluate iteration at bin endpoints, record path hash + composed (m,t).
// ---------------------------------------------------------------------------
#define FNV_P 1099511628211ull
__global__ void __launch_bounds__(512)
cpab_endpoints() {
    __shared__ float2 s_eg[NCELL * CH];
    __shared__ float2 s_eu[NCELL * CH];
    for (int i = threadIdx.x; i < NCELL * CH; i += blockDim.x) {
        s_eg[i] = g_eg[i];
        s_eu[i] = g_eu[i];
    }
    __syncthreads();

    const int e = blockIdx.x * blockDim.x + threadIdx.x;
    if (e >= CH * (KB + 1)) return;
    const int c = e / (KB + 1);
    const int j = e - c * (KB + 1);

    float q = (float)j * (1.0f / 256.0f);   // exact
    unsigned long long h = 1469598103934665603ull;
    float m = 1.0f, t = 0.0f;

    #pragma unroll 1
    for (int st = 0; st < 10; ++st) {
        int c0 = cell16(q);
        float2 g = s_eg[(c0 << 8) + c];
        float2 u = s_eu[(c0 << 8) + c];
        float qc = __fmaf_rn(g.x, q, g.y);
        float qe = __fmaf_rn(u.x, q, u.y);
        float A = u.x, B = u.y;
        int cc[4];
        #pragma unroll
        for (int ss = 0; ss < 4; ++ss) {
            cc[ss] = cell16(qe);
            float2 v = s_eu[(cc[ss] << 8) + c];
            qe = __fmaf_rn(v.x, qe, v.y);
            A  = __fmul_rn(v.x, A);
            B  = __fmaf_rn(v.x, B, v.y);
        }
        int c1 = cell16(qc);
        bool stay = (c1 == c0);
        h = (h ^ (unsigned long long)c0) * FNV_P;
        h = (h ^ (unsigned long long)(c1 + 16)) * FNV_P;
        float am, bm;
        if (stay) {
            am = g.x; bm = g.y; q = qc;
        } else {
            #pragma unroll
            for (int ss = 0; ss < 4; ++ss)
                h = (h ^ (unsigned long long)(cc[ss] + 32 + 16 * ss)) * FNV_P;
            am = A; bm = B; q = qe;
        }
        m = __fmul_rn(am, m);
        t = __fmaf_rn(am, t, bm);
    }
    g_ep[e].m = m;
    g_ep[e].t = t;
    g_ep[e].h = h;
}

// ---------------------------------------------------------------------------
// K1c: build bin table; invalid bins get NaN sentinel.
// ---------------------------------------------------------------------------
__global__ void cpab_binbuild() {
    int b = blockIdx.x * blockDim.x + threadIdx.x;
    if (b >= CH * KB) return;
    int c = b >> 12, j = b & (KB - 1);
    EndPt L = g_ep[c * (KB + 1) + j];
    EndPt R = g_ep[c * (KB + 1) + j + 1];
    bool valid = (L.h == R.h) &&
                 (__float_as_int(L.m) == __float_as_int(R.m)) &&
                 (__float_as_int(L.t) == __float_as_int(R.t)) &&
                 (L.m > 0.0f) && (g_flag != 0);
    g_bins[b] = valid ? make_float2(L.m, L.t)
                      : make_float2(__int_as_float(0x7fc00000), 0.0f);
}

// ---------------------------------------------------------------------------
// K2: pass 1 — table lookup; invalid elements compacted to queue.
// ---------------------------------------------------------------------------
__global__ void __launch_bounds__(512, 3)
cpab_pass1(const float* __restrict__ x, const float* __restrict__ theta,
           float* __restrict__ out, int n, int ntheta) {
    extern __shared__ int s_buf[];
    __shared__ int s_cnt, s_base;
    if (threadIdx.x == 0) s_cnt = 0;
    __syncthreads();

    const int stride = gridDim.x * blockDim.x;
    const int i0 = blockIdx.x * blockDim.x + threadIdx.x;

    for (int t = i0; t < ntheta; t += stride)
        out[n + t] = theta[t];

    for (int i = i0; i < n; i += stride) {
        float xv = __ldg(x + i);
        float s = __fmaf_rn(xv, 1.0f / 6.0f, 0.5f);
        if (s >= 1.0f || s <= 0.0f) { out[i] = xv; continue; }
        float q = __fmul_rn(s, 16.0f);
        int bin = min((int)__fmul_rn(q, 256.0f), KB - 1);
        int c = i & (CH - 1);
        float2 mt = __ldg(&g_bins[(c << 12) + bin]);
        if (mt.x == mt.x) {                       // valid (not NaN)
            out[i] = __fmaf_rn(__fmaf_rn(mt.x, q, mt.y), 0.375f, -3.0f);
        } else {
            int pos = atomicAdd(&s_cnt, 1);
            if (pos < BUFCAP) {
                s_buf[pos] = i;
            } else {                              // overflow safety valve
                float r = cpab_iter(q, c, g_eg, g_eu);
                out[i] = __fmaf_rn(r, 0.375f, -3.0f);
            }
        }
    }
    __syncthreads();
    int cnt = min(s_cnt, BUFCAP);
    if (threadIdx.x == 0) s_base = atomicAdd(&g_qcount, cnt);
    __syncthreads();
    int base = s_base;
    for (int k = threadIdx.x; k < cnt; k += blockDim.x)
        g_queue[base + k] = s_buf[k];
}

// ---------------------------------------------------------------------------
// K3: pass 2 — iterative engine on queued elements.
// ---------------------------------------------------------------------------
__global__ void __launch_bounds__(512, 3)
cpab_pass2(const float* __restrict__ x, float* __restrict__ out) {
    __shared__ float2 s_eg[NCELL * CH];
    __shared__ float2 s_eu[NCELL * CH];
    for (int i = threadIdx.x; i < NCELL * CH; i += blockDim.x) {
        s_eg[i] = g_eg[i];
        s_eu[i] = g_eu[i];
    }
    __syncthreads();

    const int total = g_qcount;
    const int stride = gridDim.x * blockDim.x;
    for (int t = blockIdx.x * blockDim.x + threadIdx.x; t < total; t += stride) {
        int i = g_queue[t];
        float xv = __ldg(x + i);
        float s = __fmaf_rn(xv, 1.0f / 6.0f, 0.5f);
        float q = __fmul_rn(s, 16.0f);
        int c = i & (CH - 1);
        float r = cpab_iter(q, c, s_eg, s_eu);
        out[i] = __fmaf_rn(r, 0.375f, -3.0f);
    }
}

extern "C" void kernel_launch(void* const* d_in, const int* in_sizes, int n_in,
                              void* d_out, int out_size) {
    const float* x     = (const float*)d_in[0];
    const void*  timep = d_in[4];
    const float* theta = (const float*)d_in[5];
    float* out = (float*)d_out;

    const int n = in_sizes[0];
    const int ntheta = out_size - n;

    cpab_setup<<<1, 512>>>(theta, timep);
    cpab_endpoints<<<(CH * (KB + 1) + 511) / 512, 512>>>();
    cpab_binbuild<<<(CH * KB) / 512, 512>>>();

    // Immediate (non-stream) API; idempotent, safe under graph capture.
    cudaFuncSetAttribute(cpab_pass1,
                         cudaFuncAttributeMaxDynamicSharedMemorySize,
                         BUFCAP * (int)sizeof(int));

    cpab_pass1<<<456, 512, BUFCAP * sizeof(int)>>>(x, theta, out, n, ntheta);
    cpab_pass2<<<304, 512>>>(x, out);
}

// round 8
// speedup vs baseline: 3.7570x; 1.1842x over previous
#include <cuda_runtime.h>
#include <math.h>

// CPABActivationDifferent: out[n][c] = cpab_transform(x[n][c]; theta[c]).
// Two-level piecewise-affine table (level-1: 4096 bins/ch; invalid bins
// refined x8) + compacted iterative fallback for the ~3% residual.
// B_BASIS: dgesdd N>>M path => rows 17..31 of Vt come from the LQ
// factorization (dgelq2+dorgl2), reimplemented in fp64.

#define NCELL 16
#define CH 256
#define LROWS 17
#define LCOLS 32
#define NNULL 15
#define KB 4096
#define NSUB 8
#define RCAP (1 << 19)            // max refined (invalid level-1) bins
#define QUEUE_CAP (1 << 25)       // == n exactly; cannot overflow
#define BUFCAP 16384
#define FNV_P 1099511628211ull

__device__ float2 g_eg[NCELL * CH];   // (eta, 16*gamma)
__device__ float2 g_eu[NCELL * CH];   // (1+ddt*a, 16*ddt*b)
__device__ int    g_flag, g_qcount, g_nref;
struct EndPt { float m, t; unsigned long long h; };
__device__ EndPt  g_ep[CH * (KB + 1)];
__device__ float2 g_bins[CH * KB];        // valid:(m,t)  invalid:(NaN, idx|-1)
__device__ int    g_reflist[RCAP];        // packed (c<<12)|bin
__device__ float2 g_bins2[RCAP * NSUB];   // refined sub-bins
__device__ int    g_queue[QUEUE_CAP];

__device__ __forceinline__ float decode_time(const void* tptr) {
    int iv = *(const int*)tptr;
    float fv = __int_as_float(iv);
    float af = fabsf(fv);
    if (af >= 1e-6f && af <= 1e6f) return fv;
    return (float)iv;
}
__device__ __forceinline__ double warp_sum(double v) {
    #pragma unroll
    for (int off = 16; off; off >>= 1)
        v += __shfl_xor_sync(0xffffffffu, v, off);
    return v;
}
__device__ __forceinline__ int cell16(float q) { return min((int)q, 15); }

// Exact iterative engine (identical arithmetic to the passing R6 kernel).
__device__ __forceinline__ float cpab_iter(float q, int c,
                                           const float2* eg, const float2* eu) {
    #pragma unroll 1
    for (int st = 0; st < 10; ++st) {
        int c0 = cell16(q);
        float2 g = eg[(c0 << 8) + c];
        float2 u = eu[(c0 << 8) + c];
        float qc = __fmaf_rn(g.x, q, g.y);
        float qe = __fmaf_rn(u.x, q, u.y);
        #pragma unroll
        for (int ss = 1; ss < 5; ++ss) {
            int cc = cell16(qe);
            float2 v = eu[(cc << 8) + c];
            qe = __fmaf_rn(v.x, qe, v.y);
        }
        q = (cell16(qc) == c0) ? qc : qe;
    }
    return q;
}

// Endpoint evaluation: decision-path hash + composed affine (m,t).
__device__ __forceinline__ EndPt cpab_eval(float q, int c,
                                           const float2* eg, const float2* eu) {
    unsigned long long h = 1469598103934665603ull;
    float m = 1.0f, t = 0.0f;
    #pragma unroll 1
    for (int st = 0; st < 10; ++st) {
        int c0 = cell16(q);
        float2 g = eg[(c0 << 8) + c];
        float2 u = eu[(c0 << 8) + c];
        float qc = __fmaf_rn(g.x, q, g.y);
        float qe = __fmaf_rn(u.x, q, u.y);
        float A = u.x, B = u.y;
        int cc[4];
        #pragma unroll
        for (int ss = 0; ss < 4; ++ss) {
            cc[ss] = cell16(qe);
            float2 v = eu[(cc[ss] << 8) + c];
            qe = __fmaf_rn(v.x, qe, v.y);
            A  = __fmul_rn(v.x, A);
            B  = __fmaf_rn(v.x, B, v.y);
        }
        int c1 = cell16(qc);
        bool stay = (c1 == c0);
        h = (h ^ (unsigned long long)c0) * FNV_P;
        h = (h ^ (unsigned long long)(c1 + 16)) * FNV_P;
        float am, bm;
        if (stay) { am = g.x; bm = g.y; q = qc; }
        else {
            #pragma unroll
            for (int ss = 0; ss < 4; ++ss)
                h = (h ^ (unsigned long long)(cc[ss] + 32 + 16 * ss)) * FNV_P;
            am = A; bm = B; q = qe;
        }
        m = __fmul_rn(am, m);
        t = __fmaf_rn(am, t, bm);
    }
    EndPt e; e.m = m; e.t = t; e.h = h; return e;
}

// ---------------------------------------------------------------------------
__global__ void cpab_setup(const float* __restrict__ theta,
                           const void*  __restrict__ timep) {
    __shared__ double sM[LROWS][LCOLS];
    __shared__ double stau[LROWS];
    __shared__ double sQ[NNULL][LCOLS];
    const int tid = threadIdx.x, lane = tid & 31, w = tid >> 5;

    if (tid == 0) { g_qcount = 0; g_nref = 0; g_flag = 1; }

    for (int i = tid; i < LROWS * LCOLS; i += blockDim.x)
        ((double*)sM)[i] = 0.0;
    __syncthreads();
    if (tid == 0) {
        for (int k = 1; k < NCELL; k++) {
            double xk = (double)k / (double)NCELL;
            sM[k - 1][2 * (k - 1)]     =  xk;
            sM[k - 1][2 * (k - 1) + 1] =  1.0;
            sM[k - 1][2 * k]           = -xk;
            sM[k - 1][2 * k + 1]       = -1.0;
        }
        sM[NCELL - 1][1] = 1.0;
        sM[NCELL][2 * NCELL - 2] = 1.0;
        sM[NCELL][2 * NCELL - 1] = 1.0;
    }
    __syncthreads();

    for (int i = 0; i < LROWS; i++) {
        if (w == 0) {
            double aij = sM[i][lane];
            double sq  = (lane > i) ? aij * aij : 0.0;
            sq = warp_sum(sq);
            double alpha = __shfl_sync(0xffffffffu, aij, i);
            double xnorm = sqrt(sq);
            double tau = 0.0;
            if (xnorm != 0.0) {
                double aa = fabs(alpha);
                double wv = fmax(aa, xnorm), zv = fmin(aa, xnorm);
                double r  = (zv == 0.0) ? wv
                            : wv * sqrt(1.0 + (zv / wv) * (zv / wv));
                double beta = (alpha >= 0.0) ? -r : r;
                tau = (beta - alpha) / beta;
                double inv = 1.0 / (alpha - beta);
                if (lane > i)  sM[i][lane] = aij * inv;
                if (lane == i) sM[i][i] = beta;
            }
            if (lane == 0) stau[i] = tau;
        }
        __syncthreads();
        int r = i + 1 + w;
        if (r < LROWS) {
            double tau = stau[i];
            if (tau != 0.0) {
                double v   = (lane == i) ? 1.0
                             : ((lane > i) ? sM[i][lane] : 0.0);
                double arj = (lane >= i) ? sM[r][lane] : 0.0;
                double dot = warp_sum(arj * v);
                if (lane >= i) sM[r][lane] = arj - tau * dot * v;
            }
        }
        __syncthreads();
    }
    if (w < NNULL) {
        int r = LROWS + w;
        double q = (lane == r) ? 1.0 : 0.0;
        for (int i = LROWS - 1; i >= 0; i--) {
            double tau = stau[i];
            double v = (lane == i) ? 1.0 : ((lane > i) ? sM[i][lane] : 0.0);
            double dot = warp_sum(q * v);
            q -= tau * dot * v;
        }
        sQ[w][lane] = q;
    }
    __syncthreads();

    if (tid < CH) {
        const int c = tid;
        float tf  = decode_time(timep);
        float dt  = tf / 10.0f;
        float ddt = dt / 5.0f;
        float A[LCOLS];
        #pragma unroll
        for (int j = 0; j < LCOLS; j++) {
            float s = 0.0f;
            #pragma unroll
            for (int cc = 0; cc < NNULL; cc++)
                s += theta[c * NNULL + cc] * (float)sQ[cc][j];
            A[j] = s;
        }
        bool ok = true;
        #pragma unroll
        for (int k = 0; k < NCELL; k++) {
            float a = A[2 * k], b = A[2 * k + 1];
            float eta, gam;
            if (fabsf(a) > 1e-7f) {
                eta = expf(dt * a);
                gam = __fmul_rn(__fdiv_rn(b, a), __fsub_rn(eta, 1.0f));
            } else { eta = 1.0f; gam = __fmul_rn(b, dt); }
            float ex = __fadd_rn(1.0f, __fmul_rn(ddt, a));
            if (!(ex > 0.0f) || !(eta > 0.0f)) ok = false;
            g_eg[k * CH + c] = make_float2(eta, __fmul_rn(gam, 16.0f));
            g_eu[k * CH + c] = make_float2(ex,
                                           __fmul_rn(__fmul_rn(ddt, b), 16.0f));
        }
        if (!ok) g_flag = 0;
    }
}

// ---------------------------------------------------------------------------
__global__ void __launch_bounds__(512)
cpab_endpoints() {
    __shared__ float2 s_eg[NCELL * CH], s_eu[NCELL * CH];
    for (int i = threadIdx.x; i < NCELL * CH; i += blockDim.x) {
        s_eg[i] = g_eg[i]; s_eu[i] = g_eu[i];
    }
    __syncthreads();
    const int e = blockIdx.x * blockDim.x + threadIdx.x;
    if (e >= CH * (KB + 1)) return;
    const int c = e / (KB + 1);
    const int j = e - c * (KB + 1);
    g_ep[e] = cpab_eval((float)j * (1.0f / 256.0f), c, s_eg, s_eu);
}

// ---------------------------------------------------------------------------
__global__ void cpab_binbuild() {
    int b = blockIdx.x * blockDim.x + threadIdx.x;
    if (b >= CH * KB) return;
    int c = b >> 12, j = b & (KB - 1);
    EndPt L = g_ep[c * (KB + 1) + j];
    EndPt R = g_ep[c * (KB + 1) + j + 1];
    bool valid = (L.h == R.h) &&
                 (__float_as_int(L.m) == __float_as_int(R.m)) &&
                 (__float_as_int(L.t) == __float_as_int(R.t)) &&
                 (L.m > 0.0f) && (g_flag != 0);
    if (valid) {
        g_bins[b] = make_float2(L.m, L.t);
    } else {
        int idx = atomicAdd(&g_nref, 1);
        int payload = -1;
        if (idx < RCAP) { g_reflist[idx] = (c << 12) | j; payload = idx; }
        g_bins[b] = make_float2(__int_as_float(0x7fc00000),
                                __int_as_float(payload));
    }
}

// ---------------------------------------------------------------------------
// Refine each invalid level-1 bin into NSUB sub-bins.
__global__ void __launch_bounds__(512)
cpab_refine() {
    __shared__ float2 s_eg[NCELL * CH], s_eu[NCELL * CH];
    for (int i = threadIdx.x; i < NCELL * CH; i += blockDim.x) {
        s_eg[i] = g_eg[i]; s_eu[i] = g_eu[i];
    }
    __syncthreads();
    const int nref = min(g_nref, RCAP);
    const int stride = gridDim.x * blockDim.x;
    for (int r = blockIdx.x * blockDim.x + threadIdx.x; r < nref; r += stride) {
        int cb = g_reflist[r];
        int c = cb >> 12, b = cb & (KB - 1);
        EndPt prev = cpab_eval((float)(b * NSUB) * (1.0f / 2048.0f), c,
                               s_eg, s_eu);
        #pragma unroll 1
        for (int s = 1; s <= NSUB; ++s) {
            EndPt cur = cpab_eval((float)(b * NSUB + s) * (1.0f / 2048.0f), c,
                                  s_eg, s_eu);
            bool valid = (prev.h == cur.h) &&
                         (__float_as_int(prev.m) == __float_as_int(cur.m)) &&
                         (__float_as_int(prev.t) == __float_as_int(cur.t)) &&
                         (prev.m > 0.0f) && (g_flag != 0);
            g_bins2[r * NSUB + s - 1] =
                valid ? make_float2(prev.m, prev.t)
                      : make_float2(__int_as_float(0x7fc00000), 0.0f);
            prev = cur;
        }
    }
}

// ---------------------------------------------------------------------------
// Pass 1: float4 two-level lookup; residual compacted via ballot aggregation.
// ---------------------------------------------------------------------------
__global__ void __launch_bounds__(512, 3)
cpab_pass1(const float4* __restrict__ x4, const float* __restrict__ x,
           const float* __restrict__ theta, float4* __restrict__ out4,
           float* __restrict__ out, int n4, long long n, int ntheta) {
    extern __shared__ int s_buf[];
    __shared__ int s_cnt, s_base;
    if (threadIdx.x == 0) s_cnt = 0;
    __syncthreads();

    const int lane = threadIdx.x & 31;
    const int stride = gridDim.x * blockDim.x;
    const int gtid = blockIdx.x * blockDim.x + threadIdx.x;

    for (int t = gtid; t < ntheta; t += stride)
        out[n + t] = theta[t];

    // scalar tail via exact engine (rare; ≤3 elements)
    const int rem = (int)(n - (long long)n4 * 4);
    if (blockIdx.x == 0) {
        for (int t = threadIdx.x; t < rem; t += blockDim.x) {
            long long i = (long long)n4 * 4 + t;
            float xv = x[i];
            float s = __fmaf_rn(xv, 1.0f / 6.0f, 0.5f);
            if (s >= 1.0f || s <= 0.0f) { out[i] = xv; continue; }
            float r = cpab_iter(__fmul_rn(s, 16.0f), (int)(i & (CH - 1)),
                                g_eg, g_eu);
            out[i] = __fmaf_rn(r, 0.375f, -3.0f);
        }
    }

    int i4 = gtid;
    while (true) {
        bool act = (i4 < n4);
        if (!__any_sync(0xffffffffu, act)) break;
        float4 xv = act ? __ldg(x4 + i4) : make_float4(9e9f, 9e9f, 9e9f, 9e9f);
        const int cb = (i4 << 2) & (CH - 1);
        float4 res;
        float* rp = &res.x;
        const float* xp = &xv.x;

        #pragma unroll
        for (int j = 0; j < 4; ++j) {
            float xx = xp[j];
            float s = __fmaf_rn(xx, 1.0f / 6.0f, 0.5f);
            bool ood = (s >= 1.0f) || (s <= 0.0f);
            float q = ood ? 8.0f : __fmul_rn(s, 16.0f);
            bool invalid = false;
            float r = xx;
            if (!ood) {
                int bin = min((int)__fmul_rn(q, 256.0f), KB - 1);
                float2 mt = __ldg(&g_bins[((cb + j) << 12) + bin]);
                if (mt.x == mt.x) {
                    r = __fmaf_rn(__fmaf_rn(mt.x, q, mt.y), 0.375f, -3.0f);
                } else {
                    int idx = __float_as_int(mt.y);
                    if (idx >= 0) {
                        int sub = min(max((int)__fmul_rn(q, 2048.0f)
                                          - (bin << 3), 0), NSUB - 1);
                        float2 m2 = __ldg(&g_bins2[idx * NSUB + sub]);
                        if (m2.x == m2.x)
                            r = __fmaf_rn(__fmaf_rn(m2.x, q, m2.y),
                                          0.375f, -3.0f);
                        else invalid = true;
                    } else invalid = true;
                }
            }
            // ballot-aggregated queue push (1 smem atomic per warp per slot)
            unsigned msk = __ballot_sync(0xffffffffu, invalid);
            if (msk) {
                int cnt = __popc(msk);
                int pre = __popc(msk & ((1u << lane) - 1u));
                int src = __ffs(msk) - 1;
                int basev = 0;
                if (lane == src) basev = atomicAdd(&s_cnt, cnt);
                basev = __shfl_sync(0xffffffffu, basev, src);
                if (invalid) {
                    int pos = basev + pre;
                    int i = (i4 << 2) + j;
                    if (pos < BUFCAP) {
                        s_buf[pos] = i;
                        r = 0.0f;                 // pass2 overwrites
                    } else {                      // overflow valve: exact path
                        r = __fmaf_rn(cpab_iter(q, cb + j, g_eg, g_eu),
                                      0.375f, -3.0f);
                    }
                }
            }
            rp[j] = r;
        }
        if (act) out4[i4] = res;
        i4 += stride;
    }

    __syncthreads();
    int cnt = min(s_cnt, BUFCAP);
    if (threadIdx.x == 0) s_base = atomicAdd(&g_qcount, cnt);
    __syncthreads();
    int base = s_base;
    for (int k = threadIdx.x; k < cnt; k += blockDim.x)
        g_queue[base + k] = s_buf[k];
}

// ---------------------------------------------------------------------------
__global__ void __launch_bounds__(512, 3)
cpab_pass2(const float* __restrict__ x, float* __restrict__ out) {
    __shared__ float2 s_eg[NCELL * CH], s_eu[NCELL * CH];
    for (int i = threadIdx.x; i < NCELL * CH; i += blockDim.x) {
        s_eg[i] = g_eg[i]; s_eu[i] = g_eu[i];
    }
    __syncthreads();
    const int total = g_qcount;
    const int stride = gridDim.x * blockDim.x;
    for (int t = blockIdx.x * blockDim.x + threadIdx.x; t < total; t += stride) {
        int i = g_queue[t];
        float xv = __ldg(x + i);
        float s = __fmaf_rn(xv, 1.0f / 6.0f, 0.5f);
        float q = __fmul_rn(s, 16.0f);
        float r = cpab_iter(q, i & (CH - 1), s_eg, s_eu);
        out[i] = __fmaf_rn(r, 0.375f, -3.0f);
    }
}

extern "C" void kernel_launch(void* const* d_in, const int* in_sizes, int n_in,
                              void* d_out, int out_size) {
    const float* x     = (const float*)d_in[0];
    const void*  timep = d_in[4];
    const float* theta = (const float*)d_in[5];
    float* out = (float*)d_out;

    const long long n = (long long)in_sizes[0];
    const int ntheta = out_size - (int)n;
    const int n4 = (int)(n >> 2);

    cpab_setup<<<1, 512>>>(theta, timep);
    cpab_endpoints<<<(CH * (KB + 1) + 511) / 512, 512>>>();
    cpab_binbuild<<<(CH * KB) / 512, 512>>>();
    cpab_refine<<<456, 512>>>();

    cudaFuncSetAttribute(cpab_pass1,
                         cudaFuncAttributeMaxDynamicSharedMemorySize,
                         BUFCAP * (int)sizeof(int));
    cpab_pass1<<<456, 512, BUFCAP * sizeof(int)>>>(
        (const float4*)x, x, theta, (float4*)out, out, n4, n, ntheta);
    cpab_pass2<<<304, 512>>>(x, out);
}